// round 16
// baseline (speedup 1.0000x reference)
#include <cuda_runtime.h>

// EfficientGCN preprocess on GB300 — best-measured structure (v4: smem-tiled,
// per-(t,v) threads, streaming STG.64) + proven cheap math (A&S acos minimax,
// __fdividef). The op is HBM-write-drain bound (~138MB mandatory fp32 writes);
// this is the converged configuration.
//
// x: (N=128, C=3, T=300, V=25, M=2) fp32, conn: int32[25]
// out: (N, 3, 6, T, V, M) fp32

#define N_ 128
#define C_ 3
#define T_ 300
#define V_ 25
#define RPT 10            // t-rows computed per tile
#define TILE_ROWS 12      // RPT + 2 halo
#define TILES_PER_N 30    // 300 / 10
#define ROWF 50           // floats per (t) row  (V*M)
#define CSLAB 15000       // floats per channel slab (T*ROWF)
#define SM_CH 600         // floats per channel in smem (TILE_ROWS*ROWF)

__device__ __forceinline__ float acos_fast(float x)
{
    // Abramowitz & Stegun 4.4.46: acos(a) = sqrt(1-a)*p7(a), |err| <= 2e-8
    float ax = fabsf(x);
    float p = -0.0012624911f;
    p = fmaf(p, ax,  0.0066700901f);
    p = fmaf(p, ax, -0.0170881256f);
    p = fmaf(p, ax,  0.0308918810f);
    p = fmaf(p, ax, -0.0501743046f);
    p = fmaf(p, ax,  0.0889789874f);
    p = fmaf(p, ax, -0.2145988016f);
    p = fmaf(p, ax,  1.5707963050f);
    float r = sqrtf(1.0f - ax) * p;
    return (x >= 0.0f) ? r : (3.14159265358979f - r);
}

__global__ __launch_bounds__(256, 6) void egcn_preprocess_v11(
    const float* __restrict__ x,
    const int* __restrict__ conn,
    float* __restrict__ out)
{
    __shared__ float sm[C_ * SM_CH];          // 1800 floats = 7.2 KB

    const int tid  = threadIdx.x;
    const int n    = blockIdx.x / TILES_PER_N;
    const int tile = blockIdx.x % TILES_PER_N;
    const int t0   = tile * RPT;

    const float* xn = x + n * (C_ * CSLAB);

    // ---- stage tile into smem ----
    if (t0 + TILE_ROWS <= T_) {
        // fast path: 3 channels x 600 contiguous floats = 450 float4, aligned
        #pragma unroll
        for (int k = 0; k < 2; ++k) {
            int idx = tid + k * 256;
            if (idx < 450) {
                int c   = idx / 150;
                int rem = idx - c * 150;
                const float4* src = (const float4*)(xn + c * CSLAB + t0 * ROWF);
                ((float4*)(sm + c * SM_CH))[rem] = src[rem];
            }
        }
    } else {
        // last tile (t0 = 290): per-float2 row clamp
        for (int idx = tid; idx < C_ * TILE_ROWS * V_; idx += 256) {
            int c   = idx / (TILE_ROWS * V_);
            int rem = idx - c * (TILE_ROWS * V_);
            int r   = rem / V_;
            int v   = rem - r * V_;
            int gt  = t0 + r; if (gt > T_ - 1) gt = T_ - 1;
            ((float2*)(sm + c * SM_CH + r * ROWF))[v] =
                ((const float2*)(xn + c * CSLAB + gt * ROWF))[v];
        }
    }
    __syncthreads();

    if (tid >= RPT * V_) return;              // 250 active compute threads

    const int r = tid / V_;                   // 0..9
    const int v = tid - r * V_;               // 0..24
    const int t = t0 + r;
    const int pv = conn[v];

    const float sel = (t < T_ - 2) ? 1.0f : 0.0f;

    float2 a[3], cen[3], par[3], d1[3], d2[3], bv[3];
#pragma unroll
    for (int c = 0; c < C_; ++c) {
        const float* base = sm + c * SM_CH + r * ROWF;
        a[c]   = ((const float2*)base)[v];
        cen[c] = ((const float2*)base)[1];
        par[c] = ((const float2*)base)[pv];
        float2 n1 = ((const float2*)(base + ROWF))[v];       // t+1 (halo)
        float2 n2 = ((const float2*)(base + 2 * ROWF))[v];   // t+2 (halo)
        d1[c] = make_float2((n1.x - a[c].x) * sel, (n1.y - a[c].y) * sel);
        d2[c] = make_float2((n2.x - a[c].x) * sel, (n2.y - a[c].y) * sel);
        bv[c] = make_float2(a[c].x - par[c].x, a[c].y - par[c].y);
    }

    float sx = bv[0].x * bv[0].x + bv[1].x * bv[1].x + bv[2].x * bv[2].x;
    float sy = bv[0].y * bv[0].y + bv[1].y * bv[1].y + bv[2].y * bv[2].y;
    float rlx = __fdividef(1.0f, sqrtf(sx) + 1e-4f);
    float rly = __fdividef(1.0f, sqrtf(sy) + 1e-4f);

    float2 ang[3];
#pragma unroll
    for (int c = 0; c < C_; ++c) {
        ang[c].x = acos_fast(bv[c].x * rlx);
        ang[c].y = acos_fast(bv[c].y * rly);
    }

    // ---- 18 streaming STG.64, each slab contiguous across the block ----
    const int ostride = T_ * V_;                          // 7500 float2 per (b,c2)
    float2* ob = (float2*)out + (size_t)n * 18 * ostride + t * V_ + v;

#pragma unroll
    for (int c = 0; c < C_; ++c) {
        __stcs(ob + (c     ) * ostride, a[c]);                                  // joint: x
        __stcs(ob + (c + 3 ) * ostride,
               make_float2(a[c].x - cen[c].x, a[c].y - cen[c].y));              // x - center
        __stcs(ob + (c + 6 ) * ostride, d1[c]);                                 // v1
        __stcs(ob + (c + 9 ) * ostride, d2[c]);                                 // v2
        __stcs(ob + (c + 12) * ostride, bv[c]);                                 // bone vec
        __stcs(ob + (c + 15) * ostride, ang[c]);                                // bone angle
    }
}

extern "C" void kernel_launch(void* const* d_in, const int* in_sizes, int n_in,
                              void* d_out, int out_size)
{
    const float* x  = (const float*)d_in[0];
    const int* conn = (const int*)d_in[1];
    float* out      = (float*)d_out;

    const int blocks = N_ * TILES_PER_N;     // 3840
    egcn_preprocess_v11<<<blocks, 256>>>(x, conn, out);
}